// round 13
// baseline (speedup 1.0000x reference)
#include <cuda_runtime.h>

// Shapes fixed by the dataset: u (B=64, L=8192), ev (K=32, L), lam (K)
#define L      8192
#define NB     64
#define NK     32
#define HALF   4096   // L/2
#define KD     2048   // number of odd d < L/2
#define NBLK   128    // grid size (all co-resident: 1 block/SM, 128 <= 148)

// Device scratch (no allocs allowed)
__device__ float g_ct2[KD];    // (2/L)*cot(pi*(2k+1)/L)
__device__ float g_P[L];       // P[l] = sum_k lam_k ev[k][l]
__device__ float g_Po[HALF];   // P at odd l
__device__ float g_Pe[HALF];   // P at even l
__device__ float g_pa2[NBLK];  // half-row Re partials
__device__ float g_pc2[NBLK];  // half-row Im partials
__device__ int   g_cnt;        // grid-barrier epoch counter

// ---------------------------------------------------------------------------
// Fused persistent kernel: 128 blocks x 1024 threads, all resident.
// Phase 1 (every block, balanced):
//   a/c: block bx -> batch b = bx>>1, half = bx&1 -> g_pa2[bx], g_pc2[bx].
//   P:   block bx -> l in [bx*64, bx*64+64), k-parallel park in smem + reduce.
//   ct2: 16-entry chunk per block.
// Grid barrier: atomic epoch counter + PLAIN volatile spin (no __nanosleep —
// its wakeup quantization is an unmodeled multi-µs suspect).
// Phase 2: R12-identical 4m x 32k rolling register tile, except CT is staged
// into smem with the SA/SB staging (kills 8 per-thread mid-loop L2 exposures).
__global__ void __launch_bounds__(1024, 1) kfused(const float* __restrict__ u,
                                                  const float* __restrict__ ev,
                                                  const float* __restrict__ lam,
                                                  float* __restrict__ out) {
    __shared__ alignas(16) float SA[2112];
    __shared__ alignas(16) float SB[2120];
    __shared__ alignas(16) float CTs[2048];
    __shared__ alignas(16) float red2[32 * 68];   // also reused as PS in phase 1
    __shared__ float Ps[64], aS[NB], cS[NB], Qs[64];
    __shared__ float wa[32], wc[32];

    const int t  = threadIdx.x;
    const int bx = blockIdx.x;

    // ======================= Phase 1 =======================
    {
        float* PS = red2;                    // 32 x 64 floats (k-major partials)

        // -- issue both global loads early (independent streams) --
        const int b    = bx >> 1;
        const int half = bx & 1;
        const int i    = half * 1024 + t;    // float4 index in u row (2048/row)
        float4 uv = ((const float4*)(u + (size_t)b * L))[i];

        float4 e4;
        const int k  = t >> 4;               // only t<512 used (k<32)
        const int lo = t & 15;
        if (t < 512)
            e4 = ((const float4*)ev)[k * (L / 4) + bx * 16 + lo];

        // -- a/c partial --
        float x1 = (float)(4 * i + 1) * (1.0f / (float)L);
        float x3 = (float)(4 * i + 3) * (1.0f / (float)L);
        float c1 = __fdividef(cospif(x1), sinpif(x1));
        float c3 = __fdividef(cospif(x3), sinpif(x3));
        float a = uv.x + uv.z;
        float c = -(uv.y * c1 + uv.w * c3);
        if (i == 0) a += (float)(L / 2) * uv.x;
#pragma unroll
        for (int off = 16; off > 0; off >>= 1) {
            a += __shfl_down_sync(0xffffffffu, a, off);
            c += __shfl_down_sync(0xffffffffu, c, off);
        }
        const int lane = t & 31, w = t >> 5;
        if (lane == 0) { wa[w] = a; wc[w] = c; }

        // -- P partial: park lam[k]*ev in smem --
        if (t < 512) {
            float lk = __ldg(lam + k);
            float4 v; v.x = lk * e4.x; v.y = lk * e4.y; v.z = lk * e4.z; v.w = lk * e4.w;
            ((float4*)PS)[k * 16 + lo] = v;  // PS[k*64 + 4*lo + comp]
        }
        __syncthreads();

        // -- P reduce: thread q < 64 sums over k, writes l = bx*64 + q --
        if (t < 64) {
            float s = 0.0f;
#pragma unroll
            for (int kk = 0; kk < NK; kk++) s += PS[kk * 64 + t];
            const int l = bx * 64 + t;
            g_P[l] = s;
            if (l & 1) g_Po[l >> 1] = s; else g_Pe[l >> 1] = s;
        } else if (t < 96) {
            // -- a/c final reduce (warp 2, lanes = t-64) --
            float av = wa[t - 64], cv = wc[t - 64];
#pragma unroll
            for (int off = 16; off > 0; off >>= 1) {
                av += __shfl_down_sync(0xffffffffu, av, off);
                cv += __shfl_down_sync(0xffffffffu, cv, off);
            }
            if (t == 64) { g_pa2[bx] = av; g_pc2[bx] = cv; }
        } else if (t < 112) {
            // -- ct2 chunk: idx in [bx*16, bx*16+16) --
            int idx = bx * 16 + (t - 96);
            float x = (float)(2 * idx + 1) * (1.0f / (float)L);
            g_ct2[idx] = (2.0f / (float)L) * __fdividef(cospif(x), sinpif(x));
        }
        __syncthreads();   // red2 reused in phase 2
    }

    // ======================= Grid barrier =======================
    __threadfence();                        // publish phase-1 writes
    if (t == 0) {
        int old = atomicAdd(&g_cnt, 1);
        int target = ((old >> 7) + 1) << 7; // round old+1 up to multiple of 128
        while (*(volatile int*)&g_cnt < target) { }   // plain spin, no nanosleep
    }
    __syncthreads();

    // ======================= Phase 2 =======================
    const int p  = bx >> 6;
    const int m0 = (bx & 63) * 64;

    // Stage shifted copies of the opposite-parity half of P + the CT table:
    //   A(m,k) = S[m+k+p]    -> SA[x] = S[(m0+p+x) & 4095],       A = SA[mm+k]
    //   B(m,k) = S[m-k-1+p]  -> SB[y] = S[(m0+p-2052+y) & 4095],  B = SB[mm-k+2051]
    {
        const float* S = p ? g_Pe : g_Po;
        const int baseA = m0 + p;
        const int baseB = m0 + p - 2052 + HALF;   // keep positive before mask
#pragma unroll
        for (int x = t; x < 2112; x += 1024) SA[x] = S[(baseA + x) & (HALF - 1)];
#pragma unroll
        for (int y = t; y < 2120; y += 1024) SB[y] = S[(baseB + y) & (HALF - 1)];
        CTs[t]        = g_ct2[t];
        CTs[t + 1024] = g_ct2[t + 1024];
    }
    if (t < NB) {
        aS[t] = g_pa2[2 * t] + g_pa2[2 * t + 1];
        cS[t] = g_pc2[2 * t] + g_pc2[2 * t + 1];
    } else if (t < NB + 64) {
        int mm = t - NB;
        Ps[mm] = g_P[2 * (m0 + mm) + p];
    }
    __syncthreads();

    const int ly = t & 15;              // m-subtile: m = m0 + 4*ly + r
    const int j  = t >> 4;              // 0..63, k-range [32j, 32j+32)
    const float4* SA4 = (const float4*)SA;
    const float4* SB4 = (const float4*)SB;
    const float4* CT4 = (const float4*)CTs;

    const int xa0 = ly + 8 * j;         // A float4 base at kt=0
    const int xb0 = 512 + ly - 8 * j;   // B low float4 base at kt=0

    float4 A0 = SA4[xa0];               // a0..a3 for current kt
    float4 B1 = SB4[xb0 + 1];           // b4..b7 for current kt

    float p0 = 0.f, p1 = 0.f, p2 = 0.f, p3 = 0.f;   // + accumulators (C*a)
    float n0 = 0.f, n1 = 0.f, n2 = 0.f, n3 = 0.f;   // - accumulators (C*b)
#pragma unroll
    for (int kt = 0; kt < 8; kt++) {
        float4 A1 = SA4[xa0 + kt + 1];  // a4..a7
        float4 B0 = SB4[xb0 - kt];      // b0..b3
        float4 C  = CT4[8 * j + kt];
        float a0 = A0.x, a1 = A0.y, a2 = A0.z, a3 = A0.w;
        float a4 = A1.x, a5 = A1.y, a6 = A1.z;
        float b0 = B0.x, b1 = B0.y, b2 = B0.z, b3 = B0.w;
        float b4 = B1.x, b5 = B1.y, b6 = B1.z;
        // accP[r] += C[s]*a[r+s];  accN[r] += C[s]*b[3+r-s]
        p0 = fmaf(C.x, a0, p0); n0 = fmaf(C.x, b3, n0);
        p0 = fmaf(C.y, a1, p0); n0 = fmaf(C.y, b2, n0);
        p0 = fmaf(C.z, a2, p0); n0 = fmaf(C.z, b1, n0);
        p0 = fmaf(C.w, a3, p0); n0 = fmaf(C.w, b0, n0);
        p1 = fmaf(C.x, a1, p1); n1 = fmaf(C.x, b4, n1);
        p1 = fmaf(C.y, a2, p1); n1 = fmaf(C.y, b3, n1);
        p1 = fmaf(C.z, a3, p1); n1 = fmaf(C.z, b2, n1);
        p1 = fmaf(C.w, a4, p1); n1 = fmaf(C.w, b1, n1);
        p2 = fmaf(C.x, a2, p2); n2 = fmaf(C.x, b5, n2);
        p2 = fmaf(C.y, a3, p2); n2 = fmaf(C.y, b4, n2);
        p2 = fmaf(C.z, a4, p2); n2 = fmaf(C.z, b3, n2);
        p2 = fmaf(C.w, a5, p2); n2 = fmaf(C.w, b2, n2);
        p3 = fmaf(C.x, a3, p3); n3 = fmaf(C.x, b6, n3);
        p3 = fmaf(C.y, a4, p3); n3 = fmaf(C.y, b5, n3);
        p3 = fmaf(C.z, a5, p3); n3 = fmaf(C.z, b4, n3);
        p3 = fmaf(C.w, a6, p3); n3 = fmaf(C.w, b3, n3);
        A0 = A1;                        // rolling reuse: A window +1, B window -1
        B1 = B0;
    }
    float acc0 = p0 - n0, acc1 = p1 - n1, acc2 = p2 - n2, acc3 = p3 - n3;

    // Lanes 0-15 of each warp absorb lanes 16-31 (same ly, j+1).
    acc0 += __shfl_down_sync(0xffffffffu, acc0, 16);
    acc1 += __shfl_down_sync(0xffffffffu, acc1, 16);
    acc2 += __shfl_down_sync(0xffffffffu, acc2, 16);
    acc3 += __shfl_down_sync(0xffffffffu, acc3, 16);

    const int lane = t & 31, w = t >> 5;
    if (lane < 16) {
        float4 v; v.x = acc0; v.y = acc1; v.z = acc2; v.w = acc3;
        ((float4*)(red2 + w * 68))[lane] = v;     // red2[w*68 + 4*ly + r]
    }
    __syncthreads();

    if (t < 64) {
        float s = 0.0f;
#pragma unroll
        for (int w2 = 0; w2 < 32; w2++) s += red2[w2 * 68 + t];
        Qs[t] = s;                       // ct2 already carries 2/L
    }
    __syncthreads();

    // 64 b x 64 m outputs, 4 per thread
#pragma unroll
    for (int r = 0; r < 4; r++) {
        int idx = r * 1024 + t;
        int b   = idx >> 6;
        int mm  = idx & 63;
        out[(size_t)b * L + 2 * (m0 + mm) + p] =
            fmaf(aS[b], Ps[mm], cS[b] * Qs[mm]);
    }
}

// ---------------------------------------------------------------------------
extern "C" void kernel_launch(void* const* d_in, const int* in_sizes, int n_in,
                              void* d_out, int out_size) {
    const float* u   = (const float*)d_in[0];  // (64, 8192)
    const float* ev  = (const float*)d_in[1];  // (32, 8192)
    const float* lam = (const float*)d_in[2];  // (32,)
    float* out = (float*)d_out;                // (64, 8192)

    kfused<<<NBLK, 1024>>>(u, ev, lam, out);
}

// round 14
// speedup vs baseline: 1.0239x; 1.0239x over previous
#include <cuda_runtime.h>

// Shapes fixed by the dataset: u (B=64, L=8192), ev (K=32, L), lam (K)
#define L      8192
#define NB     64
#define NK     32
#define HALF   4096   // L/2
#define KD     2048   // number of odd d < L/2
#define NBLK   128    // grid size (all co-resident: 1 block/SM, 128 <= 148)

// Device scratch (no allocs allowed)
__device__ float g_P[L];       // P[l] = sum_k lam_k ev[k][l]
__device__ float g_Po[HALF];   // P at odd l
__device__ float g_Pe[HALF];   // P at even l
__device__ float g_pa2[NBLK];  // half-row Re partials
__device__ float g_pc2[NBLK];  // half-row Im partials
__device__ int   g_cnt;        // grid-barrier epoch counter

// ---------------------------------------------------------------------------
// Fused persistent kernel: 128 blocks x 1024 threads, all resident.
// Phase 1 (every block):
//   - thread t computes cot at d = 4t+1, 4t+3 -> fills the ENTIRE ct2 table
//     locally in smem (CTs[2t], CTs[2t+1]); no global ct2 at all.
//   - a/c half-row partial (half=1 blocks get their cot values from the
//     mirror identity cot(pi*l/L) = -cot(pi*(L-l)/L) via CTs after sync).
//   - P chunk l in [bx*64, bx*64+64): k-parallel park in smem + reduce.
// Grid barrier (atomic epoch counter + nanosleep spin).
// Phase 2: 4m x 32k register tile as TWO independent rolling chains
//   (kt 0..3 and 4..7) -> 2x independent LDS->FFMA streams per warp.
__global__ void __launch_bounds__(1024, 1) kfused(const float* __restrict__ u,
                                                  const float* __restrict__ ev,
                                                  const float* __restrict__ lam,
                                                  float* __restrict__ out) {
    __shared__ alignas(16) float SA[2112];
    __shared__ alignas(16) float SB[2120];
    __shared__ alignas(16) float CTs[2048];       // local ct2 table
    __shared__ alignas(16) float red2[32 * 68];   // also reused as PS in phase 1
    __shared__ float Ps[64], aS[NB], cS[NB], Qs[64];
    __shared__ float wa[32], wc[32];

    const int t  = threadIdx.x;
    const int bx = blockIdx.x;

    // ======================= Phase 1 =======================
    {
        float* PS = red2;                    // 32 x 64 floats (k-major partials)

        // -- issue both global loads early (independent streams) --
        const int b    = bx >> 1;
        const int half = bx & 1;
        const int i    = half * 1024 + t;    // float4 index in u row (2048/row)
        float4 uv = ((const float4*)(u + (size_t)b * L))[i];

        float4 e4;
        const int k  = t >> 4;               // only t<512 used (k<32)
        const int lo = t & 15;
        if (t < 512)
            e4 = ((const float4*)ev)[k * (L / 4) + bx * 16 + lo];

        // -- full local CT table: thread t -> entries 2t, 2t+1 (d=4t+1, 4t+3)
        float x1 = (float)(4 * t + 1) * (1.0f / (float)L);
        float x3 = (float)(4 * t + 3) * (1.0f / (float)L);
        float c1 = __fdividef(cospif(x1), sinpif(x1));   // cot(pi*(4t+1)/L)
        float c3 = __fdividef(cospif(x3), sinpif(x3));   // cot(pi*(4t+3)/L)
        CTs[2 * t]     = (2.0f / (float)L) * c1;
        CTs[2 * t + 1] = (2.0f / (float)L) * c3;

        // -- P partial: park lam[k]*ev in smem --
        if (t < 512) {
            float lk = __ldg(lam + k);
            float4 v; v.x = lk * e4.x; v.y = lk * e4.y; v.z = lk * e4.z; v.w = lk * e4.w;
            ((float4*)PS)[k * 16 + lo] = v;  // PS[k*64 + 4*lo + comp]
        }
        __syncthreads();

        // -- a/c partial (cot via mirror for half=1) --
        float cot1, cot3;
        if (half == 0) { cot1 = c1; cot3 = c3; }
        else {
            // l = 4096+4t+1 -> -cot at d=4095-4t (k=2047-2t); similarly 4093-4t
            cot1 = -(float)(L / 2) * 0.5f * (CTs[2047 - 2 * t] * (float)L) * (1.0f / (float)(L / 2)); // simplify below
            cot1 = -((float)L * 0.5f) * CTs[2047 - 2 * t];
            cot3 = -((float)L * 0.5f) * CTs[2046 - 2 * t];
        }
        float a = uv.x + uv.z;
        float c = -(uv.y * cot1 + uv.w * cot3);
        if (i == 0) a += (float)(L / 2) * uv.x;
#pragma unroll
        for (int off = 16; off > 0; off >>= 1) {
            a += __shfl_down_sync(0xffffffffu, a, off);
            c += __shfl_down_sync(0xffffffffu, c, off);
        }
        const int lane = t & 31, w = t >> 5;
        if (lane == 0) { wa[w] = a; wc[w] = c; }

        // -- P reduce: thread q < 64 sums over k, writes l = bx*64 + q --
        if (t < 64) {
            float s = 0.0f;
#pragma unroll
            for (int kk = 0; kk < NK; kk++) s += PS[kk * 64 + t];
            const int l = bx * 64 + t;
            g_P[l] = s;
            if (l & 1) g_Po[l >> 1] = s; else g_Pe[l >> 1] = s;
        }
        __syncthreads();

        if (t >= 64 && t < 96) {
            // -- a/c final reduce (warp 2, lanes = t-64) --
            float av = wa[t - 64], cv = wc[t - 64];
#pragma unroll
            for (int off = 16; off > 0; off >>= 1) {
                av += __shfl_down_sync(0xffffffffu, av, off);
                cv += __shfl_down_sync(0xffffffffu, cv, off);
            }
            if (t == 64) { g_pa2[bx] = av; g_pc2[bx] = cv; }
        }
    }

    // ======================= Grid barrier =======================
    __threadfence();                        // publish phase-1 writes
    if (t == 0) {
        int old = atomicAdd(&g_cnt, 1);
        int target = ((old >> 7) + 1) << 7; // round old+1 up to multiple of 128
        while (*(volatile int*)&g_cnt < target) __nanosleep(64);
    }
    __syncthreads();

    // ======================= Phase 2 =======================
    const int p  = bx >> 6;
    const int m0 = (bx & 63) * 64;

    // Stage shifted copies of the opposite-parity half of P:
    //   A(m,k) = S[m+k+p]    -> SA[x] = S[(m0+p+x) & 4095],       A = SA[mm+k]
    //   B(m,k) = S[m-k-1+p]  -> SB[y] = S[(m0+p-2052+y) & 4095],  B = SB[mm-k+2051]
    {
        const float* S = p ? g_Pe : g_Po;
        const int baseA = m0 + p;
        const int baseB = m0 + p - 2052 + HALF;   // keep positive before mask
#pragma unroll
        for (int x = t; x < 2112; x += 1024) SA[x] = S[(baseA + x) & (HALF - 1)];
#pragma unroll
        for (int y = t; y < 2120; y += 1024) SB[y] = S[(baseB + y) & (HALF - 1)];
    }
    if (t < NB) {
        aS[t] = g_pa2[2 * t] + g_pa2[2 * t + 1];
        cS[t] = g_pc2[2 * t] + g_pc2[2 * t + 1];
    } else if (t < NB + 64) {
        int mm = t - NB;
        Ps[mm] = g_P[2 * (m0 + mm) + p];
    }
    __syncthreads();

    const int ly = t & 15;              // m-subtile: m = m0 + 4*ly + r
    const int j  = t >> 4;              // 0..63, k-range [32j, 32j+32)
    const float4* SA4 = (const float4*)SA;
    const float4* SB4 = (const float4*)SB;
    const float4* CT4 = (const float4*)CTs;

    const int xa0 = ly + 8 * j;         // A float4 base at kt=0
    const int xb0 = 512 + ly - 8 * j;   // B low float4 base at kt=0

    // Two independent rolling chains: chain a = kt 0..3, chain b = kt 4..7.
    float4 A0a = SA4[xa0],     B1a = SB4[xb0 + 1];
    float4 A0b = SA4[xa0 + 4], B1b = SB4[xb0 - 3];

    float p0a=0.f,p1a=0.f,p2a=0.f,p3a=0.f, n0a=0.f,n1a=0.f,n2a=0.f,n3a=0.f;
    float p0b=0.f,p1b=0.f,p2b=0.f,p3b=0.f, n0b=0.f,n1b=0.f,n2b=0.f,n3b=0.f;

#pragma unroll
    for (int kt = 0; kt < 4; kt++) {
        // ---- chain a (global kt) ----
        {
            float4 A1 = SA4[xa0 + kt + 1];
            float4 B0 = SB4[xb0 - kt];
            float4 C  = CT4[8 * j + kt];
            float a0=A0a.x,a1=A0a.y,a2=A0a.z,a3=A0a.w,a4=A1.x,a5=A1.y,a6=A1.z;
            float b0=B0.x,b1=B0.y,b2=B0.z,b3=B0.w,b4=B1a.x,b5=B1a.y,b6=B1a.z;
            p0a=fmaf(C.x,a0,p0a); n0a=fmaf(C.x,b3,n0a);
            p0a=fmaf(C.y,a1,p0a); n0a=fmaf(C.y,b2,n0a);
            p0a=fmaf(C.z,a2,p0a); n0a=fmaf(C.z,b1,n0a);
            p0a=fmaf(C.w,a3,p0a); n0a=fmaf(C.w,b0,n0a);
            p1a=fmaf(C.x,a1,p1a); n1a=fmaf(C.x,b4,n1a);
            p1a=fmaf(C.y,a2,p1a); n1a=fmaf(C.y,b3,n1a);
            p1a=fmaf(C.z,a3,p1a); n1a=fmaf(C.z,b2,n1a);
            p1a=fmaf(C.w,a4,p1a); n1a=fmaf(C.w,b1,n1a);
            p2a=fmaf(C.x,a2,p2a); n2a=fmaf(C.x,b5,n2a);
            p2a=fmaf(C.y,a3,p2a); n2a=fmaf(C.y,b4,n2a);
            p2a=fmaf(C.z,a4,p2a); n2a=fmaf(C.z,b3,n2a);
            p2a=fmaf(C.w,a5,p2a); n2a=fmaf(C.w,b2,n2a);
            p3a=fmaf(C.x,a3,p3a); n3a=fmaf(C.x,b6,n3a);
            p3a=fmaf(C.y,a4,p3a); n3a=fmaf(C.y,b5,n3a);
            p3a=fmaf(C.z,a5,p3a); n3a=fmaf(C.z,b4,n3a);
            p3a=fmaf(C.w,a6,p3a); n3a=fmaf(C.w,b3,n3a);
            A0a = A1; B1a = B0;
        }
        // ---- chain b (global kt+4) ----
        {
            float4 A1 = SA4[xa0 + kt + 5];
            float4 B0 = SB4[xb0 - 4 - kt];
            float4 C  = CT4[8 * j + 4 + kt];
            float a0=A0b.x,a1=A0b.y,a2=A0b.z,a3=A0b.w,a4=A1.x,a5=A1.y,a6=A1.z;
            float b0=B0.x,b1=B0.y,b2=B0.z,b3=B0.w,b4=B1b.x,b5=B1b.y,b6=B1b.z;
            p0b=fmaf(C.x,a0,p0b); n0b=fmaf(C.x,b3,n0b);
            p0b=fmaf(C.y,a1,p0b); n0b=fmaf(C.y,b2,n0b);
            p0b=fmaf(C.z,a2,p0b); n0b=fmaf(C.z,b1,n0b);
            p0b=fmaf(C.w,a3,p0b); n0b=fmaf(C.w,b0,n0b);
            p1b=fmaf(C.x,a1,p1b); n1b=fmaf(C.x,b4,n1b);
            p1b=fmaf(C.y,a2,p1b); n1b=fmaf(C.y,b3,n1b);
            p1b=fmaf(C.z,a3,p1b); n1b=fmaf(C.z,b2,n1b);
            p1b=fmaf(C.w,a4,p1b); n1b=fmaf(C.w,b1,n1b);
            p2b=fmaf(C.x,a2,p2b); n2b=fmaf(C.x,b5,n2b);
            p2b=fmaf(C.y,a3,p2b); n2b=fmaf(C.y,b4,n2b);
            p2b=fmaf(C.z,a4,p2b); n2b=fmaf(C.z,b3,n2b);
            p2b=fmaf(C.w,a5,p2b); n2b=fmaf(C.w,b2,n2b);
            p3b=fmaf(C.x,a3,p3b); n3b=fmaf(C.x,b6,n3b);
            p3b=fmaf(C.y,a4,p3b); n3b=fmaf(C.y,b5,n3b);
            p3b=fmaf(C.z,a5,p3b); n3b=fmaf(C.z,b4,n3b);
            p3b=fmaf(C.w,a6,p3b); n3b=fmaf(C.w,b3,n3b);
            A0b = A1; B1b = B0;
        }
    }
    float acc0 = (p0a - n0a) + (p0b - n0b);
    float acc1 = (p1a - n1a) + (p1b - n1b);
    float acc2 = (p2a - n2a) + (p2b - n2b);
    float acc3 = (p3a - n3a) + (p3b - n3b);

    // Lanes 0-15 of each warp absorb lanes 16-31 (same ly, j+1).
    acc0 += __shfl_down_sync(0xffffffffu, acc0, 16);
    acc1 += __shfl_down_sync(0xffffffffu, acc1, 16);
    acc2 += __shfl_down_sync(0xffffffffu, acc2, 16);
    acc3 += __shfl_down_sync(0xffffffffu, acc3, 16);

    const int lane = t & 31, w = t >> 5;
    if (lane < 16) {
        float4 v; v.x = acc0; v.y = acc1; v.z = acc2; v.w = acc3;
        ((float4*)(red2 + w * 68))[lane] = v;     // red2[w*68 + 4*ly + r]
    }
    __syncthreads();

    if (t < 64) {
        float s = 0.0f;
#pragma unroll
        for (int w2 = 0; w2 < 32; w2++) s += red2[w2 * 68 + t];
        Qs[t] = s;                       // CTs already carries 2/L
    }
    __syncthreads();

    // 64 b x 64 m outputs, 4 per thread
#pragma unroll
    for (int r = 0; r < 4; r++) {
        int idx = r * 1024 + t;
        int b   = idx >> 6;
        int mm  = idx & 63;
        out[(size_t)b * L + 2 * (m0 + mm) + p] =
            fmaf(aS[b], Ps[mm], cS[b] * Qs[mm]);
    }
}

// ---------------------------------------------------------------------------
extern "C" void kernel_launch(void* const* d_in, const int* in_sizes, int n_in,
                              void* d_out, int out_size) {
    const float* u   = (const float*)d_in[0];  // (64, 8192)
    const float* ev  = (const float*)d_in[1];  // (32, 8192)
    const float* lam = (const float*)d_in[2];  // (32,)
    float* out = (float*)d_out;                // (64, 8192)

    kfused<<<NBLK, 1024>>>(u, ev, lam, out);
}